// round 14
// baseline (speedup 1.0000x reference)
#include <cuda_runtime.h>
#include <math_constants.h>

// Problem constants
#define ROWS      512          // B*C = 64*8
#define LEN       131072       // L  (= 2^17, so 1/L is exact in fp64)
#define CHUNKS    16           // blocks per row
#define TPB       128
#define NBLK      (ROWS * CHUNKS)           // 8192
#define V4_ROW    (LEN / 4)                 // 32768 float4 per row
#define V4_CHUNK  (V4_ROW / CHUNKS)         // 2048 float4 per chunk

// Per-block partials, row-major per block: [blk][0..6] = s1,s2,s3,s4,sabs,max,min
// Padded to 8 doubles (64B) so each block's partials occupy exactly one line.
__device__ __align__(64) double g_part[NBLK][8];

__global__ void __launch_bounds__(TPB, 12) stat_pass1(const float4* __restrict__ x) {
    const int blk   = blockIdx.x;
    const int row   = blk >> 4;       // / CHUNKS
    const int chunk = blk & 15;       // % CHUNKS
    const float4* p = x + (size_t)row * V4_ROW + (size_t)chunk * V4_CHUNK;

    // 2-lane accumulators (x absorbs .x/.z, y absorbs .y/.w)
    float a1x = 0.f, a1y = 0.f, a2x = 0.f, a2y = 0.f;
    float a3x = 0.f, a3y = 0.f, a4x = 0.f, a4y = 0.f;
    float sabs = 0.f;
    float mx = -CUDART_INF_F;
    float mn =  CUDART_INF_F;

#define ACC(val, L) do {                              \
        float xv = (val);                             \
        float x2 = xv * xv;                           \
        a1##L += xv;                                  \
        a2##L += x2;                                  \
        a3##L  = fmaf(x2, xv, a3##L);                 \
        a4##L  = fmaf(x2, x2, a4##L);                 \
        sabs  += fabsf(xv);                           \
        mx = fmaxf(mx, xv);                           \
        mn = fminf(mn, xv);                           \
    } while (0)

    // __ldcs: input is touched exactly once — evict-first keeps L2 free.
#pragma unroll 4
    for (int i = threadIdx.x; i < V4_CHUNK; i += TPB) {
        float4 v = __ldcs(p + i);
        ACC(v.x, x); ACC(v.y, y);
        ACC(v.z, x); ACC(v.w, y);
    }
#undef ACC

    float t1 = a1x + a1y;
    float t2 = a2x + a2y;
    float t3 = a3x + a3y;
    float t4 = a4x + a4y;

    // warp reduce 7 values
#pragma unroll
    for (int off = 16; off > 0; off >>= 1) {
        t1   += __shfl_down_sync(0xffffffffu, t1,   off);
        t2   += __shfl_down_sync(0xffffffffu, t2,   off);
        t3   += __shfl_down_sync(0xffffffffu, t3,   off);
        t4   += __shfl_down_sync(0xffffffffu, t4,   off);
        sabs += __shfl_down_sync(0xffffffffu, sabs, off);
        mx = fmaxf(mx, __shfl_down_sync(0xffffffffu, mx, off));
        mn = fminf(mn, __shfl_down_sync(0xffffffffu, mn, off));
    }

    __shared__ float sm[7][TPB / 32];
    const int wid = threadIdx.x >> 5;
    const int lid = threadIdx.x & 31;
    if (lid == 0) {
        sm[0][wid] = t1; sm[1][wid] = t2; sm[2][wid] = t3; sm[3][wid] = t4;
        sm[4][wid] = sabs; sm[5][wid] = mx; sm[6][wid] = mn;
    }
    __syncthreads();

    if (threadIdx.x == 0) {
        float r1 = sm[0][0], r2 = sm[1][0], r3 = sm[2][0], r4 = sm[3][0];
        float ra = sm[4][0], rx = sm[5][0], rn = sm[6][0];
#pragma unroll
        for (int w = 1; w < TPB / 32; w++) {
            r1 += sm[0][w]; r2 += sm[1][w]; r3 += sm[2][w]; r4 += sm[3][w];
            ra += sm[4][w];
            rx = fmaxf(rx, sm[5][w]);
            rn = fminf(rn, sm[6][w]);
        }
        // 7 contiguous doubles: one 64B line, single coalesced store group.
        g_part[blk][0] = (double)r1;
        g_part[blk][1] = (double)r2;
        g_part[blk][2] = (double)r3;
        g_part[blk][3] = (double)r4;
        g_part[blk][4] = (double)ra;
        g_part[blk][5] = (double)rx;
        g_part[blk][6] = (double)rn;
    }
}

// One 32-thread block per row. Lanes 0..15 each own one chunk's partials —
// 56 contiguous bytes each. Warp-shuffle reduce in double; lane 0 finalizes
// (double for cancellation-prone moment assembly, fp32 for ratios/sqrts).
__global__ void __launch_bounds__(32) stat_pass2(float* __restrict__ out) {
    const int row  = blockIdx.x;
    const int lane = threadIdx.x;

    double s1 = 0.0, s2 = 0.0, s3 = 0.0, s4 = 0.0, sa = 0.0;
    double mx = -CUDART_INF;
    double mn =  CUDART_INF;
    if (lane < CHUNKS) {
        const double* p = g_part[row * CHUNKS + lane];
        // Contiguous 64B-aligned row: compiler can issue wide loads.
        const double2 d01 = *reinterpret_cast<const double2*>(p + 0);
        const double2 d23 = *reinterpret_cast<const double2*>(p + 2);
        const double2 d45 = *reinterpret_cast<const double2*>(p + 4);
        s1 = d01.x; s2 = d01.y;
        s3 = d23.x; s4 = d23.y;
        sa = d45.x; mx = d45.y;
        mn = p[6];
    }

#pragma unroll
    for (int off = 8; off > 0; off >>= 1) {
        s1 += __shfl_down_sync(0xffffffffu, s1, off);
        s2 += __shfl_down_sync(0xffffffffu, s2, off);
        s3 += __shfl_down_sync(0xffffffffu, s3, off);
        s4 += __shfl_down_sync(0xffffffffu, s4, off);
        sa += __shfl_down_sync(0xffffffffu, sa, off);
        mx = fmax(mx, __shfl_down_sync(0xffffffffu, mx, off));
        mn = fmin(mn, __shfl_down_sync(0xffffffffu, mn, off));
    }

    if (lane != 0) return;

    // ── Double part: no divides, no sqrt — only mults/FMAs ──
    const double INV_N = 1.0 / (double)LEN;            // 2^-17, exact
    const double mean  = s1 * INV_N;
    const double msq   = s2 * INV_N;                    // E[x^2]
    const double varn  = fma(-(double)LEN * mean, mean, s2);   // sum (x-mean)^2
    const double mean2 = mean * mean;
    // m3 = s3 - 3 mean s2 + 2 n mean^3
    const double m3 = fma(2.0 * (double)LEN * mean2, mean, fma(-3.0 * mean, s2, s3));
    // m4 = s4 - 4 mean s3 + 6 mean^2 s2 - 3 n mean^4
    const double m4 = fma(-3.0 * (double)LEN * mean2, mean2,
                      fma(6.0 * mean2, s2, fma(-4.0 * mean, s3, s4)));

    // Compile-time double constants (no runtime divides)
    const double C_VAR  = 1.0 / ((double)LEN - 1.0);
    const double C_SKEW = (double)LEN / (((double)LEN - 1.0) * ((double)LEN - 2.0));
    const double C_KURT = (double)LEN / (((double)LEN - 1.0) * ((double)LEN - 1.0));

    const double var = varn * C_VAR;

    // ── fp32 part: fast divides / sqrts ──
    const float varf   = (float)var;
    const float msqf   = (float)msq;
    const float m3f    = (float)(m3 * C_SKEW);
    const float m4f    = (float)(m4 * C_KURT);
    const float meanab = (float)(sa * INV_N);
    const float mxf    = (float)mx;
    const float mnf    = (float)mn;

    const float rmsf  = sqrtf(msqf);
    const float sdf   = sqrtf(varf);
    const float rvar  = 1.0f / varf;
    const float rma   = 1.0f / meanab;
    const float rrms  = 1.0f / rmsf;

    const float skew  = m3f * rvar * (1.0f / sdf);      // m3*C / sd^3
    const float kurt  = fmaf(m4f * rvar, rvar, -3.0f);  // m4*C / var^2 - 3
    const float absmx = fmaxf(fabsf(mxf), fabsf(mnf));
    const float crest = absmx * rrms;
    const float impls = (mxf - mnf) * rma;
    const float shape = rmsf * rma;

    // Output layout: out[b, stat*C + c], C=8, 10 stats -> 80 per b-row
    const int b = row >> 3;
    const int c = row & 7;
    float* o = out + b * 80 + c;
    o[0]  = (float)mean;
    o[8]  = mxf;
    o[16] = mnf;
    o[24] = rmsf;
    o[32] = varf;
    o[40] = skew;
    o[48] = kurt;
    o[56] = crest;
    o[64] = impls;
    o[72] = shape;
}

extern "C" void kernel_launch(void* const* d_in, const int* in_sizes, int n_in,
                              void* d_out, int out_size) {
    const float4* x = (const float4*)d_in[0];
    float* out = (float*)d_out;
    stat_pass1<<<NBLK, TPB>>>(x);
    stat_pass2<<<ROWS, 32>>>(out);
}

// round 15
// speedup vs baseline: 1.0370x; 1.0370x over previous
#include <cuda_runtime.h>
#include <math_constants.h>

// Problem constants
#define ROWS      512          // B*C = 64*8
#define LEN       131072       // L  (= 2^17, so 1/L is exact in fp64)
#define CHUNKS    8            // blocks per row
#define TPB       256
#define NBLK      (ROWS * CHUNKS)           // 4096
#define V4_ROW    (LEN / 4)                 // 32768 float4 per row
#define V4_CHUNK  (V4_ROW / CHUNKS)         // 4096 float4 per chunk

// Packed f32x2 ops (sm_103a FFMA2/FADD2 path — PTX-only, ptxas won't auto-fuse)
#define X2_MUL(d, a, b) \
    asm("mul.rn.f32x2 %0, %1, %2;" : "=l"(d) : "l"(a), "l"(b))
#define X2_ADD(d, a, b) \
    asm("add.rn.f32x2 %0, %1, %2;" : "=l"(d) : "l"(a), "l"(b))
#define X2_FMA(d, a, b, c) \
    asm("fma.rn.f32x2 %0, %1, %2, %3;" : "=l"(d) : "l"(a), "l"(b), "l"(c))
#define X2_UNPACK(lo, hi, v) \
    asm("mov.b64 {%0, %1}, %2;" : "=f"(lo), "=f"(hi) : "l"(v))

// Per-block partials, row-major per block: [blk][0..6] = s1,s2,s3,s4,sabs,max,min
// Padded to 8 doubles (64B) so each block's partials occupy exactly one line.
__device__ __align__(64) double g_part[NBLK][8];

__global__ void __launch_bounds__(TPB, 6) stat_pass1(const ulonglong2* __restrict__ x) {
    const int blk   = blockIdx.x;
    const int row   = blk >> 3;       // / CHUNKS
    const int chunk = blk & 7;        // % CHUNKS
    const ulonglong2* p = x + (size_t)row * V4_ROW + (size_t)chunk * V4_CHUNK;

    // Packed accumulators: lane0 absorbs .x/.z, lane1 absorbs .y/.w —
    // identical summation tree to the scalar 2-lane champion.
    unsigned long long a1 = 0ull, a2 = 0ull, a3 = 0ull, a4 = 0ull;
    float sabs = 0.f;
    float mx = -CUDART_INF_F;
    float mn =  CUDART_INF_F;

#define ACCP(P) do {                                   \
        unsigned long long _x2;                        \
        X2_MUL(_x2, (P), (P));                         \
        X2_ADD(a1, a1, (P));                           \
        X2_ADD(a2, a2, _x2);                           \
        X2_FMA(a3, _x2, (P), a3);                      \
        X2_FMA(a4, _x2, _x2, a4);                      \
        float _lo, _hi;                                \
        X2_UNPACK(_lo, _hi, (P));                      \
        sabs += fabsf(_lo);                            \
        sabs += fabsf(_hi);                            \
        mx = fmaxf(mx, _lo); mx = fmaxf(mx, _hi);      \
        mn = fminf(mn, _lo); mn = fminf(mn, _hi);      \
    } while (0)

    // __ldcs: input is touched exactly once — evict-first keeps L2 free.
#pragma unroll 4
    for (int i = threadIdx.x; i < V4_CHUNK; i += TPB) {
        ulonglong2 v = __ldcs(p + i);
        ACCP(v.x);    // (x, y)
        ACCP(v.y);    // (z, w)
    }
#undef ACCP

    // fold packed lanes (pairwise, same order as champion)
    float a1x, a1y, a2x, a2y, a3x, a3y, a4x, a4y;
    X2_UNPACK(a1x, a1y, a1);
    X2_UNPACK(a2x, a2y, a2);
    X2_UNPACK(a3x, a3y, a3);
    X2_UNPACK(a4x, a4y, a4);
    float t1 = a1x + a1y;
    float t2 = a2x + a2y;
    float t3 = a3x + a3y;
    float t4 = a4x + a4y;

    // warp reduce 7 values
#pragma unroll
    for (int off = 16; off > 0; off >>= 1) {
        t1   += __shfl_down_sync(0xffffffffu, t1,   off);
        t2   += __shfl_down_sync(0xffffffffu, t2,   off);
        t3   += __shfl_down_sync(0xffffffffu, t3,   off);
        t4   += __shfl_down_sync(0xffffffffu, t4,   off);
        sabs += __shfl_down_sync(0xffffffffu, sabs, off);
        mx = fmaxf(mx, __shfl_down_sync(0xffffffffu, mx, off));
        mn = fminf(mn, __shfl_down_sync(0xffffffffu, mn, off));
    }

    __shared__ float sm[7][TPB / 32];
    const int wid = threadIdx.x >> 5;
    const int lid = threadIdx.x & 31;
    if (lid == 0) {
        sm[0][wid] = t1; sm[1][wid] = t2; sm[2][wid] = t3; sm[3][wid] = t4;
        sm[4][wid] = sabs; sm[5][wid] = mx; sm[6][wid] = mn;
    }
    __syncthreads();

    if (threadIdx.x == 0) {
        float r1 = sm[0][0], r2 = sm[1][0], r3 = sm[2][0], r4 = sm[3][0];
        float ra = sm[4][0], rx = sm[5][0], rn = sm[6][0];
#pragma unroll
        for (int w = 1; w < TPB / 32; w++) {
            r1 += sm[0][w]; r2 += sm[1][w]; r3 += sm[2][w]; r4 += sm[3][w];
            ra += sm[4][w];
            rx = fmaxf(rx, sm[5][w]);
            rn = fminf(rn, sm[6][w]);
        }
        // 7 contiguous doubles: one 64B line, single coalesced store group.
        g_part[blk][0] = (double)r1;
        g_part[blk][1] = (double)r2;
        g_part[blk][2] = (double)r3;
        g_part[blk][3] = (double)r4;
        g_part[blk][4] = (double)ra;
        g_part[blk][5] = (double)rx;
        g_part[blk][6] = (double)rn;
    }
}

// One 32-thread block per row. Lanes 0..7 each own one chunk's partials —
// 56 contiguous bytes each (~one memory round-trip per lane). Warp-shuffle
// reduce in double; lane 0 finalizes (double for cancellation-prone moment
// assembly, fp32 for ratios/sqrts).
__global__ void __launch_bounds__(32) stat_pass2(float* __restrict__ out) {
    const int row  = blockIdx.x;
    const int lane = threadIdx.x;

    double s1 = 0.0, s2 = 0.0, s3 = 0.0, s4 = 0.0, sa = 0.0;
    double mx = -CUDART_INF;
    double mn =  CUDART_INF;
    if (lane < CHUNKS) {
        const double* p = g_part[row * CHUNKS + lane];
        const double2 d01 = *reinterpret_cast<const double2*>(p + 0);
        const double2 d23 = *reinterpret_cast<const double2*>(p + 2);
        const double2 d45 = *reinterpret_cast<const double2*>(p + 4);
        s1 = d01.x; s2 = d01.y;
        s3 = d23.x; s4 = d23.y;
        sa = d45.x; mx = d45.y;
        mn = p[6];
    }

#pragma unroll
    for (int off = 4; off > 0; off >>= 1) {
        s1 += __shfl_down_sync(0xffffffffu, s1, off);
        s2 += __shfl_down_sync(0xffffffffu, s2, off);
        s3 += __shfl_down_sync(0xffffffffu, s3, off);
        s4 += __shfl_down_sync(0xffffffffu, s4, off);
        sa += __shfl_down_sync(0xffffffffu, sa, off);
        mx = fmax(mx, __shfl_down_sync(0xffffffffu, mx, off));
        mn = fmin(mn, __shfl_down_sync(0xffffffffu, mn, off));
    }

    if (lane != 0) return;

    // ── Double part: no divides, no sqrt — only mults/FMAs ──
    const double INV_N = 1.0 / (double)LEN;            // 2^-17, exact
    const double mean  = s1 * INV_N;
    const double msq   = s2 * INV_N;                    // E[x^2]
    const double varn  = fma(-(double)LEN * mean, mean, s2);   // sum (x-mean)^2
    const double mean2 = mean * mean;
    // m3 = s3 - 3 mean s2 + 2 n mean^3
    const double m3 = fma(2.0 * (double)LEN * mean2, mean, fma(-3.0 * mean, s2, s3));
    // m4 = s4 - 4 mean s3 + 6 mean^2 s2 - 3 n mean^4
    const double m4 = fma(-3.0 * (double)LEN * mean2, mean2,
                      fma(6.0 * mean2, s2, fma(-4.0 * mean, s3, s4)));

    // Compile-time double constants (no runtime divides)
    const double C_VAR  = 1.0 / ((double)LEN - 1.0);
    const double C_SKEW = (double)LEN / (((double)LEN - 1.0) * ((double)LEN - 2.0));
    const double C_KURT = (double)LEN / (((double)LEN - 1.0) * ((double)LEN - 1.0));

    const double var = varn * C_VAR;

    // ── fp32 part: fast divides / sqrts ──
    const float varf   = (float)var;
    const float msqf   = (float)msq;
    const float m3f    = (float)(m3 * C_SKEW);
    const float m4f    = (float)(m4 * C_KURT);
    const float meanab = (float)(sa * INV_N);
    const float mxf    = (float)mx;
    const float mnf    = (float)mn;

    const float rmsf  = sqrtf(msqf);
    const float sdf   = sqrtf(varf);
    const float rvar  = 1.0f / varf;
    const float rma   = 1.0f / meanab;
    const float rrms  = 1.0f / rmsf;

    const float skew  = m3f * rvar * (1.0f / sdf);      // m3*C / sd^3
    const float kurt  = fmaf(m4f * rvar, rvar, -3.0f);  // m4*C / var^2 - 3
    const float absmx = fmaxf(fabsf(mxf), fabsf(mnf));
    const float crest = absmx * rrms;
    const float impls = (mxf - mnf) * rma;
    const float shape = rmsf * rma;

    // Output layout: out[b, stat*C + c], C=8, 10 stats -> 80 per b-row
    const int b = row >> 3;
    const int c = row & 7;
    float* o = out + b * 80 + c;
    o[0]  = (float)mean;
    o[8]  = mxf;
    o[16] = mnf;
    o[24] = rmsf;
    o[32] = varf;
    o[40] = skew;
    o[48] = kurt;
    o[56] = crest;
    o[64] = impls;
    o[72] = shape;
}

extern "C" void kernel_launch(void* const* d_in, const int* in_sizes, int n_in,
                              void* d_out, int out_size) {
    const ulonglong2* x = (const ulonglong2*)d_in[0];
    float* out = (float*)d_out;
    stat_pass1<<<NBLK, TPB>>>(x);
    stat_pass2<<<ROWS, 32>>>(out);
}